// round 10
// baseline (speedup 1.0000x reference)
#include <cuda_runtime.h>
#include <cstdint>

namespace {

constexpr int B    = 1024;
constexpr int NP   = 22;
constexpr int DD   = 3;
constexpr int H    = 64;
constexpr int L    = 5;
constexpr int EPB  = NP * (NP - 1);  // 462 real edges
constexpr int EPBP = 464;            // padded (2 garbage edges, never reduced)
constexpr int NE4  = 116;            // quad-edge threads: t -> {t, t+116, t+232, t+348}
constexpr int HS   = 68;             // h/P/Q stride
constexpr int MS   = 68;             // m stride: lane stride 68 ≡ 4 (mod 32) -> conflict-free per quarter-warp
constexpr int NT   = 128;            // 4 warps, 512 regs/thread budget

// ---- shared weight region offsets (floats), edge-phase layout ----
constexpr int W_WE1  = 0;            // 130*64 = 8320
constexpr int W_WE2  = 8320;         // 64*64  = 4096
constexpr int W_WC1  = 12416;        // 64*64  = 4096
constexpr int W_WATT = 16512;
constexpr int W_WC2  = 16576;
constexpr int W_BE1  = 16640;
constexpr int W_BE2  = 16704;
constexpr int W_BC1  = 16768;
constexpr int W_BATT = 16832;
constexpr int W_SZ   = 16840;
// node-phase overlay
constexpr int W_WN1 = 0;             // 128*64 = 8192
constexpr int W_WN2 = 8192;          // 64*64  = 4096
constexpr int W_BN1 = 12288;
constexpr int W_BN2 = 12352;

struct __align__(16) Smem {
  float W[W_SZ];              //  67,360 B
  float h[NP * HS];           //   5,984 B
  float P[NP * HS];           //   5,984 B  P_i = h_i @ We1[0:64]; reused as agg
  float Q[NP * HS];           //   5,984 B  Q_i = h_i @ We1[64:128]
  float m[EPBP * MS];         // 126,208 B  m1 then GATED m2 (padded rows)
  float ea[EPBP];             //   1,856 B
  float trans[EPBP * DD];     //   5,568 B
  float coord[NP * DD];       //     264 B
  float scr[(NT / 32) * H];   //   1,024 B
};                            // ~215 KB

// ---------------- packed f32x2 helpers ----------------
__device__ __forceinline__ unsigned long long splat2(float v) {
  unsigned long long r;
  unsigned int u = __float_as_uint(v);
  asm("mov.b64 %0, {%1, %1};" : "=l"(r) : "r"(u));
  return r;
}
__device__ __forceinline__ unsigned long long pack2(float a, float b) {
  unsigned long long r;
  asm("mov.b64 %0, {%1, %2};" : "=l"(r) : "r"(__float_as_uint(a)), "r"(__float_as_uint(b)));
  return r;
}
__device__ __forceinline__ unsigned long long ffma2(unsigned long long a,
                                                    unsigned long long b,
                                                    unsigned long long c) {
  unsigned long long d;
  asm("fma.rn.f32x2 %0, %1, %2, %3;" : "=l"(d) : "l"(a), "l"(b), "l"(c));
  return d;
}
__device__ __forceinline__ void unpack2(unsigned long long v, float& lo, float& hi) {
  unsigned int a, b;
  asm("mov.b64 {%0, %1}, %2;" : "=r"(a), "=r"(b) : "l"(v));
  lo = __uint_as_float(a);
  hi = __uint_as_float(b);
}
__device__ __forceinline__ float silu_f(float x) {
  return __fdividef(x, 1.0f + __expf(-x));
}

// full-width (64 outputs) k-step, FOUR edges: each LDS.128 feeds 8 FFMA2
__device__ __forceinline__ void gfull4(unsigned long long a0[32], unsigned long long a1[32],
                                       unsigned long long a2[32], unsigned long long a3[32],
                                       const ulonglong2* __restrict__ wrow,
                                       unsigned long long i0, unsigned long long i1,
                                       unsigned long long i2, unsigned long long i3) {
#pragma unroll
  for (int i = 0; i < 16; i++) {
    ulonglong2 u = wrow[i];                 // broadcast LDS.128 (1 wf)
    a0[2 * i]     = ffma2(i0, u.x, a0[2 * i]);
    a1[2 * i]     = ffma2(i1, u.x, a1[2 * i]);
    a2[2 * i]     = ffma2(i2, u.x, a2[2 * i]);
    a3[2 * i]     = ffma2(i3, u.x, a3[2 * i]);
    a0[2 * i + 1] = ffma2(i0, u.y, a0[2 * i + 1]);
    a1[2 * i + 1] = ffma2(i1, u.y, a1[2 * i + 1]);
    a2[2 * i + 1] = ffma2(i2, u.y, a2[2 * i + 1]);
    a3[2 * i + 1] = ffma2(i3, u.y, a3[2 * i + 1]);
  }
}

__device__ __forceinline__ void cp_f4(float* dst, const float* __restrict__ src,
                                      int nfloats, int tid) {
  float4* d = reinterpret_cast<float4*>(dst);
  const float4* s = reinterpret_cast<const float4*>(src);
  for (int i = tid; i < (nfloats >> 2); i += NT) d[i] = s[i];
}

__global__ void __launch_bounds__(NT, 1)
egnn_kernel(const float* __restrict__ t, const float* __restrict__ x,
            const float* __restrict__ h_init,
            const float* __restrict__ Wemb, const float* __restrict__ bemb,
            const float* __restrict__ We1,  const float* __restrict__ be1,
            const float* __restrict__ We2,  const float* __restrict__ be2,
            const float* __restrict__ Watt, const float* __restrict__ batt,
            const float* __restrict__ Wn1,  const float* __restrict__ bn1,
            const float* __restrict__ Wn2,  const float* __restrict__ bn2,
            const float* __restrict__ Wc1,  const float* __restrict__ bc1,
            const float* __restrict__ Wc2,
            float* __restrict__ out)
{
  extern __shared__ char smem_raw[];
  Smem& s = *reinterpret_cast<Smem*>(smem_raw);
  const int b    = blockIdx.x;
  const int tid  = threadIdx.x;
  const int w    = tid >> 5;
  const int lane = tid & 31;

  // ---------- node embedding: h = [one_hot | t] @ Wemb + bemb ----------
  const float tb = t[b];
  for (int task = tid; task < NP * H; task += NT) {
    const int i = task / H, o = task % H;
    float acc = bemb[o] + tb * Wemb[NP * H + o];
#pragma unroll
    for (int j = 0; j < NP; j++) acc += h_init[i * NP + j] * Wemb[j * H + o];
    s.h[i * HS + o] = acc;
  }
  for (int task = tid; task < NP * DD; task += NT)
    s.coord[task] = x[b * (NP * DD) + task];
  __syncthreads();

  // fixed edge attribute from INITIAL coords (padded edges get harmless garbage)
  for (int e = tid; e < EPBP; e += NT) {
    const int er = min(e, EPB - 1);
    const int r = er / (NP - 1), jj = er % (NP - 1);
    const int c = jj + (jj >= r ? 1 : 0);
    const float dx = s.coord[r * 3 + 0] - s.coord[c * 3 + 0];
    const float dy = s.coord[r * 3 + 1] - s.coord[c * 3 + 1];
    const float dz = s.coord[r * 3 + 2] - s.coord[c * 3 + 2];
    s.ea[e] = dx * dx + dy * dy + dz * dz;
  }

  for (int l = 0; l < L; l++) {
    // ---------- stage edge-phase weights ----------
    cp_f4(s.W + W_WE1,  We1 + l * 130 * H, 130 * H, tid);
    cp_f4(s.W + W_WE2,  We2 + l * H * H,   H * H,   tid);
    cp_f4(s.W + W_WC1,  Wc1 + l * H * H,   H * H,   tid);
    cp_f4(s.W + W_WATT, Watt + l * H,      H,       tid);
    cp_f4(s.W + W_WC2,  Wc2 + l * H,       H,       tid);
    cp_f4(s.W + W_BE1,  be1 + l * H,       H,       tid);
    cp_f4(s.W + W_BE2,  be2 + l * H,       H,       tid);
    cp_f4(s.W + W_BC1,  bc1 + l * H,       H,       tid);
    if (tid == 0) s.W[W_BATT] = batt[l];
    __syncthreads();

    // ---------- P/Q phase: warp-per-node (4 warps, 6 rounds) ----------
    {
      const unsigned long long* W1u =
          reinterpret_cast<const unsigned long long*>(s.W + W_WE1);
#pragma unroll 1
      for (int n = w; n < NP; n += NT / 32) {
        const float* hn = s.h + n * HS;
        unsigned long long accP = 0ull, accQ = 0ull;
#pragma unroll 4
        for (int k = 0; k < H; k++) {
          const unsigned long long hv = splat2(hn[k]);
          accP = ffma2(hv, W1u[k * 32 + lane], accP);
          accQ = ffma2(hv, W1u[(H + k) * 32 + lane], accQ);
        }
        reinterpret_cast<unsigned long long*>(s.P + n * HS)[lane] = accP;
        reinterpret_cast<unsigned long long*>(s.Q + n * HS)[lane] = accQ;
      }
    }
    __syncthreads();

    // ---------- edge phase: 4 edges per thread (t < 116) ----------
    if (tid < NE4) {
      int   eq[4], rq[4], cq[4];
      float dxq[4], dyq[4], dzq[4], radq[4], eavq[4];
      float* me[4];
      const float *Pr[4], *Qc[4];
#pragma unroll
      for (int q = 0; q < 4; q++) {
        const int e = tid + q * NE4;            // 0..463 (462,463 = padding)
        eq[q] = e;
        const int er = min(e, EPB - 1);
        const int r = er / (NP - 1), jj = er % (NP - 1);
        const int c = jj + (jj >= r ? 1 : 0);
        rq[q] = r; cq[q] = c;
        dxq[q] = s.coord[r * 3 + 0] - s.coord[c * 3 + 0];
        dyq[q] = s.coord[r * 3 + 1] - s.coord[c * 3 + 1];
        dzq[q] = s.coord[r * 3 + 2] - s.coord[c * 3 + 2];
        radq[q] = dxq[q] * dxq[q] + dyq[q] * dyq[q] + dzq[q] * dzq[q];
        eavq[q] = s.ea[e];
        me[q] = s.m + e * MS;
        Pr[q] = s.P + r * HS;
        Qc[q] = s.Q + c * HS;
      }

      // ---- m1 assembly: m1 = silu(P_r + Q_c + rad*We1[128] + ea*We1[129] + be1) ----
      {
        const float* wr = s.W + W_WE1 + 128 * H;
        const float* we = s.W + W_WE1 + 129 * H;
        const float* bb = s.W + W_BE1;
#pragma unroll
        for (int o = 0; o < H; o += 4) {
          const float4 wv = *reinterpret_cast<const float4*>(wr + o);
          const float4 ev = *reinterpret_cast<const float4*>(we + o);
          const float4 bv = *reinterpret_cast<const float4*>(bb + o);
#pragma unroll
          for (int q = 0; q < 4; q++) {
            const float4 p = *reinterpret_cast<const float4*>(Pr[q] + o);
            const float4 qv = *reinterpret_cast<const float4*>(Qc[q] + o);
            float4 sv;
            sv.x = silu_f(p.x + qv.x + radq[q] * wv.x + eavq[q] * ev.x + bv.x);
            sv.y = silu_f(p.y + qv.y + radq[q] * wv.y + eavq[q] * ev.y + bv.y);
            sv.z = silu_f(p.z + qv.z + radq[q] * wv.z + eavq[q] * ev.z + bv.z);
            sv.w = silu_f(p.w + qv.w + radq[q] * wv.w + eavq[q] * ev.w + bv.w);
            *reinterpret_cast<float4*>(me[q] + o) = sv;
          }
        }
      }

      // ---- GEMV2 (FULL width, quad): m2 = silu(m1 @ We2 + be2); gate; store gated ----
      {
        unsigned long long a0[32], a1[32], a2[32], a3[32];
        const unsigned long long* bp =
            reinterpret_cast<const unsigned long long*>(s.W + W_BE2);
#pragma unroll
        for (int i = 0; i < 32; i++) { a0[i] = bp[i]; a1[i] = bp[i]; a2[i] = bp[i]; a3[i] = bp[i]; }
        const ulonglong2* W2 = reinterpret_cast<const ulonglong2*>(s.W + W_WE2);
#pragma unroll 1
        for (int k0 = 0; k0 < H; k0 += 4) {
          const float4 v0 = *reinterpret_cast<const float4*>(me[0] + k0);
          const float4 v1 = *reinterpret_cast<const float4*>(me[1] + k0);
          const float4 v2 = *reinterpret_cast<const float4*>(me[2] + k0);
          const float4 v3 = *reinterpret_cast<const float4*>(me[3] + k0);
          gfull4(a0, a1, a2, a3, W2 + (k0 + 0) * 16,
                 splat2(v0.x), splat2(v1.x), splat2(v2.x), splat2(v3.x));
          gfull4(a0, a1, a2, a3, W2 + (k0 + 1) * 16,
                 splat2(v0.y), splat2(v1.y), splat2(v2.y), splat2(v3.y));
          gfull4(a0, a1, a2, a3, W2 + (k0 + 2) * 16,
                 splat2(v0.z), splat2(v1.z), splat2(v2.z), splat2(v3.z));
          gfull4(a0, a1, a2, a3, W2 + (k0 + 3) * 16,
                 splat2(v0.w), splat2(v1.w), splat2(v2.w), splat2(v3.w));
        }
        // epilogue per edge: silu, att dot, gate, vector store (m1 fully consumed)
#pragma unroll
        for (int q = 0; q < 4; q++) {
          unsigned long long* aq = (q == 0) ? a0 : (q == 1) ? a1 : (q == 2) ? a2 : a3;
          float att = s.W[W_BATT];
#pragma unroll
          for (int i = 0; i < 32; i++) {
            float p, qv;
            unpack2(aq[i], p, qv);
            p = silu_f(p); qv = silu_f(qv);
            att += p * s.W[W_WATT + 2 * i] + qv * s.W[W_WATT + 2 * i + 1];
            aq[i] = pack2(p, qv);
          }
          const float sg = __fdividef(1.0f, 1.0f + __expf(-att));
#pragma unroll
          for (int i = 0; i < 16; i++) {
            float p0, q0, p1, q1;
            unpack2(aq[2 * i],     p0, q0);
            unpack2(aq[2 * i + 1], p1, q1);
            *reinterpret_cast<float4*>(me[q] + 4 * i) =
                make_float4(p0 * sg, q0 * sg, p1 * sg, q1 * sg);
          }
        }
      }

      // ---- GEMVc (FULL width, quad): phi = silu(m2g @ Wc1 + bc1) . Wc2 ----
      {
        unsigned long long a0[32], a1[32], a2[32], a3[32];
        const unsigned long long* bp =
            reinterpret_cast<const unsigned long long*>(s.W + W_BC1);
#pragma unroll
        for (int i = 0; i < 32; i++) { a0[i] = bp[i]; a1[i] = bp[i]; a2[i] = bp[i]; a3[i] = bp[i]; }
        const ulonglong2* Wc = reinterpret_cast<const ulonglong2*>(s.W + W_WC1);
#pragma unroll 1
        for (int k0 = 0; k0 < H; k0 += 4) {
          const float4 v0 = *reinterpret_cast<const float4*>(me[0] + k0);
          const float4 v1 = *reinterpret_cast<const float4*>(me[1] + k0);
          const float4 v2 = *reinterpret_cast<const float4*>(me[2] + k0);
          const float4 v3 = *reinterpret_cast<const float4*>(me[3] + k0);
          gfull4(a0, a1, a2, a3, Wc + (k0 + 0) * 16,
                 splat2(v0.x), splat2(v1.x), splat2(v2.x), splat2(v3.x));
          gfull4(a0, a1, a2, a3, Wc + (k0 + 1) * 16,
                 splat2(v0.y), splat2(v1.y), splat2(v2.y), splat2(v3.y));
          gfull4(a0, a1, a2, a3, Wc + (k0 + 2) * 16,
                 splat2(v0.z), splat2(v1.z), splat2(v2.z), splat2(v3.z));
          gfull4(a0, a1, a2, a3, Wc + (k0 + 3) * 16,
                 splat2(v0.w), splat2(v1.w), splat2(v2.w), splat2(v3.w));
        }
#pragma unroll
        for (int q = 0; q < 4; q++) {
          unsigned long long* aq = (q == 0) ? a0 : (q == 1) ? a1 : (q == 2) ? a2 : a3;
          float phi = 0.0f;
#pragma unroll
          for (int i = 0; i < 32; i++) {
            float p, qv;
            unpack2(aq[i], p, qv);
            phi += silu_f(p) * s.W[W_WC2 + 2 * i] + silu_f(qv) * s.W[W_WC2 + 2 * i + 1];
          }
          const float th = tanhf(phi) * 3.0f;   // COORDS_RANGE
          const int e = eq[q];
          s.trans[e * 3 + 0] = dxq[q] * th;
          s.trans[e * 3 + 1] = dyq[q] * th;
          s.trans[e * 3 + 2] = dzq[q] * th;
        }
      }
    }
    __syncthreads();

    // ---------- stage node weights (overlay) + segment-sum ----------
    cp_f4(s.W + W_WN1, Wn1 + l * 128 * H, 128 * H, tid);
    cp_f4(s.W + W_WN2, Wn2 + l * H * H,   H * H,   tid);
    cp_f4(s.W + W_BN1, bn1 + l * H,       H,       tid);
    cp_f4(s.W + W_BN2, bn2 + l * H,       H,       tid);
    for (int task = tid; task < NP * H; task += NT) {
      const int r = task >> 6, o = task & 63;
      const float* mp = s.m + (r * (NP - 1)) * MS + o;
      float a = 0.0f;
#pragma unroll
      for (int j = 0; j < NP - 1; j++) a += mp[j * MS];   // gated m2 sum (real edges only)
      s.P[r * HS + o] = a;                  // agg reuses P
    }
    for (int task = tid; task < NP * DD; task += NT) {
      const int r = task / DD, d = task % DD;
      const float* tp = s.trans + (r * (NP - 1)) * DD + d;
      float a = 0.0f;
#pragma unroll
      for (int j = 0; j < NP - 1; j++) a += tp[j * DD];
      s.coord[task] += a;
    }
    __syncthreads();

    // ---------- node phase: warp-per-node, h += MLP([h | agg]) ----------
    {
      const unsigned long long* Wn1u =
          reinterpret_cast<const unsigned long long*>(s.W + W_WN1);
      const unsigned long long* Wn2u =
          reinterpret_cast<const unsigned long long*>(s.W + W_WN2);
      const unsigned long long bn1p =
          reinterpret_cast<const unsigned long long*>(s.W + W_BN1)[lane];
      const unsigned long long bn2p =
          reinterpret_cast<const unsigned long long*>(s.W + W_BN2)[lane];
      unsigned long long* scru = reinterpret_cast<unsigned long long*>(s.scr);
#pragma unroll 1
      for (int n = w; n < NP; n += NT / 32) {
        const float* hn = s.h + n * HS;
        const float* an = s.P + n * HS;     // agg
        unsigned long long a1 = bn1p;
#pragma unroll 2
        for (int k = 0; k < H; k++) a1 = ffma2(splat2(hn[k]), Wn1u[k * 32 + lane], a1);
#pragma unroll 2
        for (int k = 0; k < H; k++) a1 = ffma2(splat2(an[k]), Wn1u[(H + k) * 32 + lane], a1);
        float lo, hi; unpack2(a1, lo, hi);
        scru[w * 32 + lane] = pack2(silu_f(lo), silu_f(hi));
        __syncwarp();
        const float* sc = s.scr + w * H;
        unsigned long long a2 = bn2p;
#pragma unroll 2
        for (int k = 0; k < H; k++) a2 = ffma2(splat2(sc[k]), Wn2u[k * 32 + lane], a2);
        unpack2(a2, lo, hi);
        s.h[n * HS + 2 * lane]     += lo;
        s.h[n * HS + 2 * lane + 1] += hi;
        __syncwarp();
      }
    }
    __syncthreads();
  }

  // ---------- output: vel = (coord - x) - mean_over_particles ----------
  if (tid < DD) {
    float mm = 0.0f;
    for (int i = 0; i < NP; i++)
      mm += s.coord[i * DD + tid] - x[b * (NP * DD) + i * DD + tid];
    s.ea[tid] = mm * (1.0f / NP);
  }
  __syncthreads();
  for (int task = tid; task < NP * DD; task += NT) {
    out[b * (NP * DD) + task] =
        (s.coord[task] - x[b * (NP * DD) + task]) - s.ea[task % DD];
  }
}

}  // namespace

extern "C" void kernel_launch(void* const* d_in, const int* in_sizes, int n_in,
                              void* d_out, int out_size) {
  (void)in_sizes; (void)n_in; (void)out_size;
  const float* t      = (const float*)d_in[0];
  const float* x      = (const float*)d_in[1];
  const float* h_init = (const float*)d_in[2];
  // d_in[3]/d_in[4] rows/cols: fixed fully-connected pattern, derived analytically
  const float* Wemb = (const float*)d_in[5];
  const float* bemb = (const float*)d_in[6];
  const float* We1  = (const float*)d_in[7];
  const float* be1  = (const float*)d_in[8];
  const float* We2  = (const float*)d_in[9];
  const float* be2  = (const float*)d_in[10];
  const float* Watt = (const float*)d_in[11];
  const float* batt = (const float*)d_in[12];
  const float* Wn1  = (const float*)d_in[13];
  const float* bn1  = (const float*)d_in[14];
  const float* Wn2  = (const float*)d_in[15];
  const float* bn2  = (const float*)d_in[16];
  const float* Wc1  = (const float*)d_in[17];
  const float* bc1  = (const float*)d_in[18];
  const float* Wc2  = (const float*)d_in[19];

  cudaFuncSetAttribute(egnn_kernel, cudaFuncAttributeMaxDynamicSharedMemorySize,
                       (int)sizeof(Smem));
  egnn_kernel<<<B, NT, sizeof(Smem)>>>(t, x, h_init, Wemb, bemb, We1, be1, We2, be2,
                                       Watt, batt, Wn1, bn1, Wn2, bn2, Wc1, bc1, Wc2,
                                       (float*)d_out);
}

// round 12
// speedup vs baseline: 9.7790x; 9.7790x over previous
#include <cuda_runtime.h>
#include <cuda_fp16.h>
#include <cstdint>

namespace {

constexpr int B   = 1024;
constexpr int NP  = 22;
constexpr int DD  = 3;
constexpr int H   = 64;
constexpr int L   = 5;
constexpr int EPB = NP * (NP - 1);   // 462 edges
constexpr int ND  = 231;             // dual-edge threads
constexpr int HSF = 68;              // fp32 h/agg stride (floats)
constexpr int PQS = 66;              // fp16 P/Q stride (halves)
constexpr int MSH = 66;              // fp16 m stride (halves)
constexpr int NT  = 256;             // 8 warps; 2 CTAs/SM via 128-reg cap

// misc (fp32) offsets
constexpr int M_WE1R = 0;    // We1 rows 128,129 (128 floats)
constexpr int M_BE1  = 128;
constexpr int M_BE2  = 192;
constexpr int M_BC1  = 256;
constexpr int M_WATT = 320;
constexpr int M_WC2  = 384;
constexpr int M_BN1  = 448;
constexpr int M_BN2  = 512;
constexpr int M_BATT = 576;
constexpr int M_SZ   = 640;

struct __align__(16) Smem {
  float  Wm[4096];          // 16,384 B  overlay: We1lo/We1hi/We2/Wc1/Wn1lo/Wn1hi/Wn2
  float  misc[M_SZ];        //  2,560 B
  float  h[NP * HSF];       //  5,984 B
  float  agg[NP * HSF];     //  5,984 B
  float  ea[EPB];           //  1,848 B
  float  trans[EPB * DD];   //  5,544 B
  float  coord[NP * DD];    //    264 B
  __half P[NP * PQS];       //  2,904 B
  __half Q[NP * PQS];       //  2,904 B
  __half m[EPB * MSH];      // 60,984 B  m1 then GATED m2; reused as fp32 node-hidden
};                          // ~105.3 KB -> 2 CTAs/SM

// ---------------- packed f32x2 helpers ----------------
__device__ __forceinline__ unsigned long long splat2(float v) {
  unsigned long long r; unsigned int u = __float_as_uint(v);
  asm("mov.b64 %0, {%1, %1};" : "=l"(r) : "r"(u)); return r;
}
__device__ __forceinline__ unsigned long long pack2(float a, float b) {
  unsigned long long r;
  asm("mov.b64 %0, {%1, %2};" : "=l"(r) : "r"(__float_as_uint(a)), "r"(__float_as_uint(b)));
  return r;
}
__device__ __forceinline__ unsigned long long ffma2(unsigned long long a,
                                                    unsigned long long b,
                                                    unsigned long long c) {
  unsigned long long d;
  asm("fma.rn.f32x2 %0, %1, %2, %3;" : "=l"(d) : "l"(a), "l"(b), "l"(c));
  return d;
}
__device__ __forceinline__ void unpack2(unsigned long long v, float& lo, float& hi) {
  unsigned int a, b;
  asm("mov.b64 {%0, %1}, %2;" : "=r"(a), "=r"(b) : "l"(v));
  lo = __uint_as_float(a); hi = __uint_as_float(b);
}
__device__ __forceinline__ float silu_f(float x) {
  return __fdividef(x, 1.0f + __expf(-x));
}
__device__ __forceinline__ uint32_t h2pack(float a, float b) {
  __half2 h = __floats2half2_rn(a, b);
  return *reinterpret_cast<uint32_t*>(&h);
}
__device__ __forceinline__ float2 h2unpack(uint32_t u) {
  __half2 h = *reinterpret_cast<__half2*>(&u);
  return __half22float2(h);
}
__device__ __forceinline__ float2 ldh2(const __half* p) {
  return __half22float2(*reinterpret_cast<const __half2*>(p));
}
__device__ __forceinline__ void sth2(__half* p, float a, float b) {
  *reinterpret_cast<__half2*>(p) = __floats2half2_rn(a, b);
}

// half-width (32 outputs) k-step, TWO edges: each LDS.128 feeds 4 FFMA2
__device__ __forceinline__ void ghalf2(unsigned long long a0[16],
                                       unsigned long long a1[16],
                                       const ulonglong2* __restrict__ wrow,
                                       unsigned long long in0,
                                       unsigned long long in1) {
#pragma unroll
  for (int i = 0; i < 8; i++) {
    ulonglong2 u = wrow[i];                 // broadcast LDS.128
    a0[2 * i]     = ffma2(in0, u.x, a0[2 * i]);
    a1[2 * i]     = ffma2(in1, u.x, a1[2 * i]);
    a0[2 * i + 1] = ffma2(in0, u.y, a0[2 * i + 1]);
    a1[2 * i + 1] = ffma2(in1, u.y, a1[2 * i + 1]);
  }
}

__device__ __forceinline__ void cp_f4(float* dst, const float* __restrict__ src,
                                      int nfloats, int tid) {
  float4* d = reinterpret_cast<float4*>(dst);
  const float4* s = reinterpret_cast<const float4*>(src);
  for (int i = tid; i < (nfloats >> 2); i += NT) d[i] = s[i];
}

__global__ void __launch_bounds__(NT, 2)        // 128-reg cap -> 2 CTAs/SM
egnn_kernel(const float* __restrict__ t, const float* __restrict__ x,
            const float* __restrict__ h_init,
            const float* __restrict__ Wemb, const float* __restrict__ bemb,
            const float* __restrict__ We1,  const float* __restrict__ be1,
            const float* __restrict__ We2,  const float* __restrict__ be2,
            const float* __restrict__ Watt, const float* __restrict__ batt,
            const float* __restrict__ Wn1,  const float* __restrict__ bn1,
            const float* __restrict__ Wn2,  const float* __restrict__ bn2,
            const float* __restrict__ Wc1,  const float* __restrict__ bc1,
            const float* __restrict__ Wc2,
            float* __restrict__ out)
{
  extern __shared__ char smem_raw[];
  Smem& s = *reinterpret_cast<Smem*>(smem_raw);
  const int b    = blockIdx.x;
  const int tid  = threadIdx.x;
  const int w    = tid >> 5;
  const int lane = tid & 31;

  // ---------- node embedding ----------
  const float tb = t[b];
  for (int task = tid; task < NP * H; task += NT) {
    const int i = task / H, o = task % H;
    float acc = bemb[o] + tb * Wemb[NP * H + o];
#pragma unroll
    for (int j = 0; j < NP; j++) acc += h_init[i * NP + j] * Wemb[j * H + o];
    s.h[i * HSF + o] = acc;
  }
  for (int task = tid; task < NP * DD; task += NT)
    s.coord[task] = x[b * (NP * DD) + task];
  __syncthreads();

  for (int e = tid; e < EPB; e += NT) {
    const int r = e / (NP - 1), jj = e % (NP - 1);
    const int c = jj + (jj >= r ? 1 : 0);
    const float dx = s.coord[r * 3 + 0] - s.coord[c * 3 + 0];
    const float dy = s.coord[r * 3 + 1] - s.coord[c * 3 + 1];
    const float dz = s.coord[r * 3 + 2] - s.coord[c * 3 + 2];
    s.ea[e] = dx * dx + dy * dy + dz * dz;
  }

  for (int l = 0; l < L; l++) {
    // ---------- misc + Wm <- We1 rows 0:64 ----------
    __syncthreads();
    cp_f4(s.misc + M_WE1R, We1 + l * 130 * H + 128 * H, 2 * H, tid);
    cp_f4(s.misc + M_BE1,  be1 + l * H, H, tid);
    cp_f4(s.misc + M_BE2,  be2 + l * H, H, tid);
    cp_f4(s.misc + M_BC1,  bc1 + l * H, H, tid);
    cp_f4(s.misc + M_WATT, Watt + l * H, H, tid);
    cp_f4(s.misc + M_WC2,  Wc2 + l * H, H, tid);
    cp_f4(s.misc + M_BN1,  bn1 + l * H, H, tid);
    cp_f4(s.misc + M_BN2,  bn2 + l * H, H, tid);
    if (tid == 0) s.misc[M_BATT] = batt[l];
    cp_f4(s.Wm, We1 + l * 130 * H, H * H, tid);
    __syncthreads();

    // ---------- P pass: P_n = h_n @ We1[0:64] ----------
    {
      const unsigned long long* Wu = reinterpret_cast<const unsigned long long*>(s.Wm);
#pragma unroll 1
      for (int n = w; n < NP; n += NT / 32) {
        const float* hn = s.h + n * HSF;
        unsigned long long acc = 0ull;
#pragma unroll 4
        for (int k = 0; k < H; k++) acc = ffma2(splat2(hn[k]), Wu[k * 32 + lane], acc);
        float lo, hi; unpack2(acc, lo, hi);
        sth2(s.P + n * PQS + 2 * lane, lo, hi);
      }
    }
    __syncthreads();
    cp_f4(s.Wm, We1 + l * 130 * H + H * H, H * H, tid);   // rows 64:128
    __syncthreads();

    // ---------- Q pass: Q_n = h_n @ We1[64:128] ----------
    {
      const unsigned long long* Wu = reinterpret_cast<const unsigned long long*>(s.Wm);
#pragma unroll 1
      for (int n = w; n < NP; n += NT / 32) {
        const float* hn = s.h + n * HSF;
        unsigned long long acc = 0ull;
#pragma unroll 4
        for (int k = 0; k < H; k++) acc = ffma2(splat2(hn[k]), Wu[k * 32 + lane], acc);
        float lo, hi; unpack2(acc, lo, hi);
        sth2(s.Q + n * PQS + 2 * lane, lo, hi);
      }
    }
    __syncthreads();
    cp_f4(s.Wm, We2 + l * H * H, H * H, tid);
    __syncthreads();

    // ---------- edge pass A: m1 assembly + GEMV2 + gate (tid < 231) ----------
    if (tid < ND) {
      const int e0 = tid, e1 = tid + ND;
      const int r0 = e0 / (NP - 1), j0 = e0 % (NP - 1);
      const int c0 = j0 + (j0 >= r0 ? 1 : 0);
      const int r1 = e1 / (NP - 1), j1 = e1 % (NP - 1);
      const int c1 = j1 + (j1 >= r1 ? 1 : 0);
      float rad0, rad1;
      {
        const float dx0 = s.coord[r0 * 3 + 0] - s.coord[c0 * 3 + 0];
        const float dy0 = s.coord[r0 * 3 + 1] - s.coord[c0 * 3 + 1];
        const float dz0 = s.coord[r0 * 3 + 2] - s.coord[c0 * 3 + 2];
        const float dx1 = s.coord[r1 * 3 + 0] - s.coord[c1 * 3 + 0];
        const float dy1 = s.coord[r1 * 3 + 1] - s.coord[c1 * 3 + 1];
        const float dz1 = s.coord[r1 * 3 + 2] - s.coord[c1 * 3 + 2];
        rad0 = dx0 * dx0 + dy0 * dy0 + dz0 * dz0;
        rad1 = dx1 * dx1 + dy1 * dy1 + dz1 * dz1;
      }
      const float ea0 = s.ea[e0], ea1 = s.ea[e1];
      __half* me0 = s.m + e0 * MSH;
      __half* me1 = s.m + e1 * MSH;

      // m1 = silu(P_r + Q_c + rad*We1r128 + ea*We1r129 + be1)  (fp16 store)
      {
        const __half* Pr0 = s.P + r0 * PQS;
        const __half* Qc0 = s.Q + c0 * PQS;
        const __half* Pr1 = s.P + r1 * PQS;
        const __half* Qc1 = s.Q + c1 * PQS;
        const float* wr = s.misc + M_WE1R;
        const float* we = s.misc + M_WE1R + H;
        const float* bb = s.misc + M_BE1;
#pragma unroll 4
        for (int o = 0; o < H; o += 2) {
          const float2 pA = ldh2(Pr0 + o);
          const float2 qA = ldh2(Qc0 + o);
          const float2 pB = ldh2(Pr1 + o);
          const float2 qB = ldh2(Qc1 + o);
          const float w0 = wr[o], w1 = wr[o + 1];
          const float v0 = we[o], v1 = we[o + 1];
          const float b0v = bb[o], b1v = bb[o + 1];
          sth2(me0 + o, silu_f(pA.x + qA.x + rad0 * w0 + ea0 * v0 + b0v),
                        silu_f(pA.y + qA.y + rad0 * w1 + ea0 * v1 + b1v));
          sth2(me1 + o, silu_f(pB.x + qB.x + rad1 * w0 + ea1 * v0 + b0v),
                        silu_f(pB.y + qB.y + rad1 * w1 + ea1 * v1 + b1v));
        }
      }

      // GEMV2 half-width x2, m2 half-0 held as packed fp16 (16 regs/edge)
      uint32_t h0e0[16], h0e1[16];
      float att0 = s.misc[M_BATT], att1 = att0;
      unsigned long long a0[16], a1[16];
      const unsigned long long* be2p =
          reinterpret_cast<const unsigned long long*>(s.misc + M_BE2);
      const ulonglong2* W2 = reinterpret_cast<const ulonglong2*>(s.Wm);
      // half 0 (outputs 0..31)
#pragma unroll
      for (int i = 0; i < 16; i++) { a0[i] = be2p[i]; a1[i] = be2p[i]; }
#pragma unroll 2
      for (int k0 = 0; k0 < H; k0 += 2) {
        const float2 v0 = ldh2(me0 + k0);
        const float2 v1 = ldh2(me1 + k0);
        ghalf2(a0, a1, W2 + (k0 + 0) * 16, splat2(v0.x), splat2(v1.x));
        ghalf2(a0, a1, W2 + (k0 + 1) * 16, splat2(v0.y), splat2(v1.y));
      }
#pragma unroll
      for (int i = 0; i < 16; i++) {
        float p, q;
        unpack2(a0[i], p, q);
        p = silu_f(p); q = silu_f(q);
        att0 += p * s.misc[M_WATT + 2 * i] + q * s.misc[M_WATT + 2 * i + 1];
        h0e0[i] = h2pack(p, q);
        unpack2(a1[i], p, q);
        p = silu_f(p); q = silu_f(q);
        att1 += p * s.misc[M_WATT + 2 * i] + q * s.misc[M_WATT + 2 * i + 1];
        h0e1[i] = h2pack(p, q);
      }
      // half 1 (outputs 32..63)
#pragma unroll
      for (int i = 0; i < 16; i++) { a0[i] = be2p[16 + i]; a1[i] = be2p[16 + i]; }
#pragma unroll 2
      for (int k0 = 0; k0 < H; k0 += 2) {
        const float2 v0 = ldh2(me0 + k0);
        const float2 v1 = ldh2(me1 + k0);
        ghalf2(a0, a1, W2 + (k0 + 0) * 16 + 8, splat2(v0.x), splat2(v1.x));
        ghalf2(a0, a1, W2 + (k0 + 1) * 16 + 8, splat2(v0.y), splat2(v1.y));
      }
#pragma unroll
      for (int i = 0; i < 16; i++) {
        float p, q;
        unpack2(a0[i], p, q);
        p = silu_f(p); q = silu_f(q);
        att0 += p * s.misc[M_WATT + 32 + 2 * i] + q * s.misc[M_WATT + 32 + 2 * i + 1];
        a0[i] = pack2(p, q);
        unpack2(a1[i], p, q);
        p = silu_f(p); q = silu_f(q);
        att1 += p * s.misc[M_WATT + 32 + 2 * i] + q * s.misc[M_WATT + 32 + 2 * i + 1];
        a1[i] = pack2(p, q);
      }
      const float sg0 = __fdividef(1.0f, 1.0f + __expf(-att0));
      const float sg1 = __fdividef(1.0f, 1.0f + __expf(-att1));
      // store GATED m2 (all m1 reads complete)
#pragma unroll
      for (int i = 0; i < 16; i++) {
        float2 f = h2unpack(h0e0[i]);
        sth2(me0 + 2 * i, f.x * sg0, f.y * sg0);
        f = h2unpack(h0e1[i]);
        sth2(me1 + 2 * i, f.x * sg1, f.y * sg1);
        float p, q;
        unpack2(a0[i], p, q);
        sth2(me0 + 32 + 2 * i, p * sg0, q * sg0);
        unpack2(a1[i], p, q);
        sth2(me1 + 32 + 2 * i, p * sg1, q * sg1);
      }
    }
    __syncthreads();
    cp_f4(s.Wm, Wc1 + l * H * H, H * H, tid);
    __syncthreads();

    // ---------- edge pass B: GEMVc -> phi -> trans ----------
    if (tid < ND) {
      const int e0 = tid, e1 = tid + ND;
      const int r0 = e0 / (NP - 1), j0 = e0 % (NP - 1);
      const int c0 = j0 + (j0 >= r0 ? 1 : 0);
      const int r1 = e1 / (NP - 1), j1 = e1 % (NP - 1);
      const int c1 = j1 + (j1 >= r1 ? 1 : 0);
      const __half* me0 = s.m + e0 * MSH;
      const __half* me1 = s.m + e1 * MSH;
      const ulonglong2* Wc = reinterpret_cast<const ulonglong2*>(s.Wm);
      const unsigned long long* bcp =
          reinterpret_cast<const unsigned long long*>(s.misc + M_BC1);
      float phi0 = 0.0f, phi1 = 0.0f;
#pragma unroll 1
      for (int half = 0; half < 2; half++) {
        unsigned long long a0[16], a1[16];
#pragma unroll
        for (int i = 0; i < 16; i++) { a0[i] = bcp[half * 16 + i]; a1[i] = bcp[half * 16 + i]; }
#pragma unroll 2
        for (int k0 = 0; k0 < H; k0 += 2) {
          const float2 v0 = ldh2(me0 + k0);
          const float2 v1 = ldh2(me1 + k0);
          ghalf2(a0, a1, Wc + (k0 + 0) * 16 + half * 8, splat2(v0.x), splat2(v1.x));
          ghalf2(a0, a1, Wc + (k0 + 1) * 16 + half * 8, splat2(v0.y), splat2(v1.y));
        }
#pragma unroll
        for (int i = 0; i < 16; i++) {
          float p, q;
          unpack2(a0[i], p, q);
          phi0 += silu_f(p) * s.misc[M_WC2 + half * 32 + 2 * i]
                + silu_f(q) * s.misc[M_WC2 + half * 32 + 2 * i + 1];
          unpack2(a1[i], p, q);
          phi1 += silu_f(p) * s.misc[M_WC2 + half * 32 + 2 * i]
                + silu_f(q) * s.misc[M_WC2 + half * 32 + 2 * i + 1];
        }
      }
      const float th0 = tanhf(phi0) * 3.0f;   // COORDS_RANGE
      const float th1 = tanhf(phi1) * 3.0f;
#pragma unroll
      for (int d = 0; d < 3; d++) {
        s.trans[e0 * 3 + d] = (s.coord[r0 * 3 + d] - s.coord[c0 * 3 + d]) * th0;
        s.trans[e1 * 3 + d] = (s.coord[r1 * 3 + d] - s.coord[c1 * 3 + d]) * th1;
      }
    }
    __syncthreads();

    // ---------- agg (fp16 m sum) + coord; Wm <- Wn1 rows 0:64 ----------
    cp_f4(s.Wm, Wn1 + l * 128 * H, H * H, tid);
    for (int task = tid; task < NP * H; task += NT) {
      const int r = task >> 6, o = task & 63;
      const __half* mp = s.m + (r * (NP - 1)) * MSH + o;
      float a = 0.0f;
#pragma unroll
      for (int j = 0; j < NP - 1; j++) a += __half2float(mp[j * MSH]);
      s.agg[r * HSF + o] = a;
    }
    for (int task = tid; task < NP * DD; task += NT) {
      const int r = task / DD, d = task % DD;
      const float* tp = s.trans + (r * (NP - 1)) * DD + d;
      float a = 0.0f;
#pragma unroll
      for (int j = 0; j < NP - 1; j++) a += tp[j * DD];
      s.coord[task] += a;
    }
    __syncthreads();

    // ---------- node GEMV1 part 1 (h input) ----------
    unsigned long long a1v[3];
    {
      const unsigned long long* Wu = reinterpret_cast<const unsigned long long*>(s.Wm);
      const unsigned long long bn1p =
          reinterpret_cast<const unsigned long long*>(s.misc + M_BN1)[lane];
      int rnd = 0;
#pragma unroll 1
      for (int n = w; n < NP; n += NT / 32, rnd++) {
        const float* hn = s.h + n * HSF;
        unsigned long long acc = bn1p;
#pragma unroll 4
        for (int k = 0; k < H; k++) acc = ffma2(splat2(hn[k]), Wu[k * 32 + lane], acc);
        a1v[rnd] = acc;
      }
    }
    __syncthreads();
    cp_f4(s.Wm, Wn1 + l * 128 * H + H * H, H * H, tid);   // rows 64:128
    __syncthreads();

    // ---------- node GEMV1 part 2 (agg input) -> hidden (fp32 in m buffer) ----------
    {
      float* hid = reinterpret_cast<float*>(s.m);
      const unsigned long long* Wu = reinterpret_cast<const unsigned long long*>(s.Wm);
      int rnd = 0;
#pragma unroll 1
      for (int n = w; n < NP; n += NT / 32, rnd++) {
        const float* an = s.agg + n * HSF;
        unsigned long long acc = a1v[rnd];
#pragma unroll 4
        for (int k = 0; k < H; k++) acc = ffma2(splat2(an[k]), Wu[k * 32 + lane], acc);
        float lo, hi; unpack2(acc, lo, hi);
        reinterpret_cast<unsigned long long*>(hid)[n * 32 + lane] =
            pack2(silu_f(lo), silu_f(hi));
      }
    }
    __syncthreads();
    cp_f4(s.Wm, Wn2 + l * H * H, H * H, tid);
    __syncthreads();

    // ---------- node GEMV2: h += hidden @ Wn2 + bn2 ----------
    {
      const float* hid = reinterpret_cast<const float*>(s.m);
      const unsigned long long* Wu = reinterpret_cast<const unsigned long long*>(s.Wm);
      const unsigned long long bn2p =
          reinterpret_cast<const unsigned long long*>(s.misc + M_BN2)[lane];
#pragma unroll 1
      for (int n = w; n < NP; n += NT / 32) {
        const float* hn = hid + n * H;
        unsigned long long acc = bn2p;
#pragma unroll 4
        for (int k = 0; k < H; k++) acc = ffma2(splat2(hn[k]), Wu[k * 32 + lane], acc);
        float lo, hi; unpack2(acc, lo, hi);
        s.h[n * HSF + 2 * lane]     += lo;
        s.h[n * HSF + 2 * lane + 1] += hi;
      }
    }
    __syncthreads();
  }

  // ---------- output: vel = (coord - x) - mean_over_particles ----------
  if (tid < DD) {
    float mm = 0.0f;
    for (int i = 0; i < NP; i++)
      mm += s.coord[i * DD + tid] - x[b * (NP * DD) + i * DD + tid];
    s.ea[tid] = mm * (1.0f / NP);
  }
  __syncthreads();
  for (int task = tid; task < NP * DD; task += NT) {
    out[b * (NP * DD) + task] =
        (s.coord[task] - x[b * (NP * DD) + task]) - s.ea[task % DD];
  }
}

}  // namespace

extern "C" void kernel_launch(void* const* d_in, const int* in_sizes, int n_in,
                              void* d_out, int out_size) {
  (void)in_sizes; (void)n_in; (void)out_size;
  const float* t      = (const float*)d_in[0];
  const float* x      = (const float*)d_in[1];
  const float* h_init = (const float*)d_in[2];
  // d_in[3]/d_in[4] rows/cols: fixed fully-connected pattern, derived analytically
  const float* Wemb = (const float*)d_in[5];
  const float* bemb = (const float*)d_in[6];
  const float* We1  = (const float*)d_in[7];
  const float* be1  = (const float*)d_in[8];
  const float* We2  = (const float*)d_in[9];
  const float* be2  = (const float*)d_in[10];
  const float* Watt = (const float*)d_in[11];
  const float* batt = (const float*)d_in[12];
  const float* Wn1  = (const float*)d_in[13];
  const float* bn1  = (const float*)d_in[14];
  const float* Wn2  = (const float*)d_in[15];
  const float* bn2  = (const float*)d_in[16];
  const float* Wc1  = (const float*)d_in[17];
  const float* bc1  = (const float*)d_in[18];
  const float* Wc2  = (const float*)d_in[19];

  cudaFuncSetAttribute(egnn_kernel, cudaFuncAttributeMaxDynamicSharedMemorySize,
                       (int)sizeof(Smem));
  egnn_kernel<<<B, NT, sizeof(Smem)>>>(t, x, h_init, Wemb, bemb, We1, be1, We2, be2,
                                       Watt, batt, Wn1, bn1, Wn2, bn2, Wc1, bc1, Wc2,
                                       (float*)d_out);
}

// round 14
// speedup vs baseline: 9.9246x; 1.0149x over previous
#include <cuda_runtime.h>
#include <cuda_fp16.h>
#include <cstdint>

namespace {

constexpr int B   = 1024;
constexpr int NP  = 22;
constexpr int DD  = 3;
constexpr int H   = 64;
constexpr int L   = 5;
constexpr int EPB = NP * (NP - 1);   // 462 edges
constexpr int ND  = 231;             // dual-edge threads
constexpr int HSF = 68;              // fp32 h/P/Q/agg stride (floats)
constexpr int MSH = 66;              // fp16 m stride (halves)
constexpr int NT  = 256;             // 8 warps; 2 CTAs/SM via 128-reg cap

// misc (fp32) offsets
constexpr int M_WE1R = 0;    // We1 rows 128,129 (128 floats)
constexpr int M_BE1  = 128;
constexpr int M_BE2  = 192;
constexpr int M_BC1  = 256;
constexpr int M_WATT = 320;
constexpr int M_WC2  = 384;
constexpr int M_BN1  = 448;
constexpr int M_BN2  = 512;
constexpr int M_BATT = 576;
constexpr int M_SZ   = 640;

struct __align__(16) Smem {
  float  Wm[4096];          // 16,384 B  overlay: We1lo/We1hi/We2/Wc1/Wn1lo/Wn1hi/Wn2
  float  misc[M_SZ];        //  2,560 B
  float  h[NP * HSF];       //  5,984 B
  float  P[NP * HSF];       //  5,984 B  fp32 (precision-critical)
  float  Q[NP * HSF];       //  5,984 B  fp32
  float  agg[NP * HSF];     //  5,984 B
  float  ea[EPB];           //  1,848 B
  float  trans[EPB * DD];   //  5,544 B
  float  coord[NP * DD];    //    264 B
  __half m[EPB * MSH];      // 60,984 B  m1 then GATED m2; reused as fp32 node-hidden
};                          // ~108.9 KB -> 2 CTAs/SM

// ---------------- packed f32x2 helpers ----------------
__device__ __forceinline__ unsigned long long splat2(float v) {
  unsigned long long r; unsigned int u = __float_as_uint(v);
  asm("mov.b64 %0, {%1, %1};" : "=l"(r) : "r"(u)); return r;
}
__device__ __forceinline__ unsigned long long pack2(float a, float b) {
  unsigned long long r;
  asm("mov.b64 %0, {%1, %2};" : "=l"(r) : "r"(__float_as_uint(a)), "r"(__float_as_uint(b)));
  return r;
}
__device__ __forceinline__ unsigned long long ffma2(unsigned long long a,
                                                    unsigned long long b,
                                                    unsigned long long c) {
  unsigned long long d;
  asm("fma.rn.f32x2 %0, %1, %2, %3;" : "=l"(d) : "l"(a), "l"(b), "l"(c));
  return d;
}
__device__ __forceinline__ void unpack2(unsigned long long v, float& lo, float& hi) {
  unsigned int a, b;
  asm("mov.b64 {%0, %1}, %2;" : "=r"(a), "=r"(b) : "l"(v));
  lo = __uint_as_float(a); hi = __uint_as_float(b);
}
__device__ __forceinline__ float silu_f(float x) {
  return __fdividef(x, 1.0f + __expf(-x));
}
__device__ __forceinline__ uint32_t h2pack(float a, float b) {
  __half2 h = __floats2half2_rn(a, b);
  return *reinterpret_cast<uint32_t*>(&h);
}
__device__ __forceinline__ float2 h2unpack(uint32_t u) {
  __half2 h = *reinterpret_cast<__half2*>(&u);
  return __half22float2(h);
}
__device__ __forceinline__ float2 ldh2(const __half* p) {
  return __half22float2(*reinterpret_cast<const __half2*>(p));
}
__device__ __forceinline__ void sth2(__half* p, float a, float b) {
  *reinterpret_cast<__half2*>(p) = __floats2half2_rn(a, b);
}

// half-width (32 outputs) k-step, TWO edges: each LDS.128 feeds 4 FFMA2
__device__ __forceinline__ void ghalf2(unsigned long long a0[16],
                                       unsigned long long a1[16],
                                       const ulonglong2* __restrict__ wrow,
                                       unsigned long long in0,
                                       unsigned long long in1) {
#pragma unroll
  for (int i = 0; i < 8; i++) {
    ulonglong2 u = wrow[i];                 // broadcast LDS.128
    a0[2 * i]     = ffma2(in0, u.x, a0[2 * i]);
    a1[2 * i]     = ffma2(in1, u.x, a1[2 * i]);
    a0[2 * i + 1] = ffma2(in0, u.y, a0[2 * i + 1]);
    a1[2 * i + 1] = ffma2(in1, u.y, a1[2 * i + 1]);
  }
}

__device__ __forceinline__ void cp_f4(float* dst, const float* __restrict__ src,
                                      int nfloats, int tid) {
  float4* d = reinterpret_cast<float4*>(dst);
  const float4* s = reinterpret_cast<const float4*>(src);
  for (int i = tid; i < (nfloats >> 2); i += NT) d[i] = s[i];
}

__global__ void __launch_bounds__(NT, 2)        // 128-reg cap -> 2 CTAs/SM
egnn_kernel(const float* __restrict__ t, const float* __restrict__ x,
            const float* __restrict__ h_init,
            const float* __restrict__ Wemb, const float* __restrict__ bemb,
            const float* __restrict__ We1,  const float* __restrict__ be1,
            const float* __restrict__ We2,  const float* __restrict__ be2,
            const float* __restrict__ Watt, const float* __restrict__ batt,
            const float* __restrict__ Wn1,  const float* __restrict__ bn1,
            const float* __restrict__ Wn2,  const float* __restrict__ bn2,
            const float* __restrict__ Wc1,  const float* __restrict__ bc1,
            const float* __restrict__ Wc2,
            float* __restrict__ out)
{
  extern __shared__ char smem_raw[];
  Smem& s = *reinterpret_cast<Smem*>(smem_raw);
  const int b    = blockIdx.x;
  const int tid  = threadIdx.x;
  const int w    = tid >> 5;
  const int lane = tid & 31;

  // ---------- node embedding ----------
  const float tb = t[b];
  for (int task = tid; task < NP * H; task += NT) {
    const int i = task / H, o = task % H;
    float acc = bemb[o] + tb * Wemb[NP * H + o];
#pragma unroll
    for (int j = 0; j < NP; j++) acc += h_init[i * NP + j] * Wemb[j * H + o];
    s.h[i * HSF + o] = acc;
  }
  for (int task = tid; task < NP * DD; task += NT)
    s.coord[task] = x[b * (NP * DD) + task];
  __syncthreads();

  for (int e = tid; e < EPB; e += NT) {
    const int r = e / (NP - 1), jj = e % (NP - 1);
    const int c = jj + (jj >= r ? 1 : 0);
    const float dx = s.coord[r * 3 + 0] - s.coord[c * 3 + 0];
    const float dy = s.coord[r * 3 + 1] - s.coord[c * 3 + 1];
    const float dz = s.coord[r * 3 + 2] - s.coord[c * 3 + 2];
    s.ea[e] = dx * dx + dy * dy + dz * dz;
  }

  for (int l = 0; l < L; l++) {
    // ---------- misc + Wm <- We1 rows 0:64 ----------
    __syncthreads();
    cp_f4(s.misc + M_WE1R, We1 + l * 130 * H + 128 * H, 2 * H, tid);
    cp_f4(s.misc + M_BE1,  be1 + l * H, H, tid);
    cp_f4(s.misc + M_BE2,  be2 + l * H, H, tid);
    cp_f4(s.misc + M_BC1,  bc1 + l * H, H, tid);
    cp_f4(s.misc + M_WATT, Watt + l * H, H, tid);
    cp_f4(s.misc + M_WC2,  Wc2 + l * H, H, tid);
    cp_f4(s.misc + M_BN1,  bn1 + l * H, H, tid);
    cp_f4(s.misc + M_BN2,  bn2 + l * H, H, tid);
    if (tid == 0) s.misc[M_BATT] = batt[l];
    cp_f4(s.Wm, We1 + l * 130 * H, H * H, tid);
    __syncthreads();

    // ---------- P pass: P_n = h_n @ We1[0:64] (fp32) ----------
    {
      const unsigned long long* Wu = reinterpret_cast<const unsigned long long*>(s.Wm);
#pragma unroll 1
      for (int n = w; n < NP; n += NT / 32) {
        const float* hn = s.h + n * HSF;
        unsigned long long acc = 0ull;
#pragma unroll 4
        for (int k = 0; k < H; k++) acc = ffma2(splat2(hn[k]), Wu[k * 32 + lane], acc);
        reinterpret_cast<unsigned long long*>(s.P + n * HSF)[lane] = acc;
      }
    }
    __syncthreads();
    cp_f4(s.Wm, We1 + l * 130 * H + H * H, H * H, tid);   // rows 64:128
    __syncthreads();

    // ---------- Q pass: Q_n = h_n @ We1[64:128] (fp32) ----------
    {
      const unsigned long long* Wu = reinterpret_cast<const unsigned long long*>(s.Wm);
#pragma unroll 1
      for (int n = w; n < NP; n += NT / 32) {
        const float* hn = s.h + n * HSF;
        unsigned long long acc = 0ull;
#pragma unroll 4
        for (int k = 0; k < H; k++) acc = ffma2(splat2(hn[k]), Wu[k * 32 + lane], acc);
        reinterpret_cast<unsigned long long*>(s.Q + n * HSF)[lane] = acc;
      }
    }
    __syncthreads();
    cp_f4(s.Wm, We2 + l * H * H, H * H, tid);
    __syncthreads();

    // ---------- edge pass A: m1 assembly + GEMV2 + gate (tid < 231) ----------
    if (tid < ND) {
      const int e0 = tid, e1 = tid + ND;
      const int r0 = e0 / (NP - 1), j0 = e0 % (NP - 1);
      const int c0 = j0 + (j0 >= r0 ? 1 : 0);
      const int r1 = e1 / (NP - 1), j1 = e1 % (NP - 1);
      const int c1 = j1 + (j1 >= r1 ? 1 : 0);
      float rad0, rad1;
      {
        const float dx0 = s.coord[r0 * 3 + 0] - s.coord[c0 * 3 + 0];
        const float dy0 = s.coord[r0 * 3 + 1] - s.coord[c0 * 3 + 1];
        const float dz0 = s.coord[r0 * 3 + 2] - s.coord[c0 * 3 + 2];
        const float dx1 = s.coord[r1 * 3 + 0] - s.coord[c1 * 3 + 0];
        const float dy1 = s.coord[r1 * 3 + 1] - s.coord[c1 * 3 + 1];
        const float dz1 = s.coord[r1 * 3 + 2] - s.coord[c1 * 3 + 2];
        rad0 = dx0 * dx0 + dy0 * dy0 + dz0 * dz0;
        rad1 = dx1 * dx1 + dy1 * dy1 + dz1 * dz1;
      }
      const float ea0 = s.ea[e0], ea1 = s.ea[e1];
      __half* me0 = s.m + e0 * MSH;
      __half* me1 = s.m + e1 * MSH;

      // m1 = silu(P_r + Q_c + rad*We1r128 + ea*We1r129 + be1)  (fp32 in, fp16 store)
      {
        const float* Pr0 = s.P + r0 * HSF;
        const float* Qc0 = s.Q + c0 * HSF;
        const float* Pr1 = s.P + r1 * HSF;
        const float* Qc1 = s.Q + c1 * HSF;
        const float* wr = s.misc + M_WE1R;
        const float* we = s.misc + M_WE1R + H;
        const float* bb = s.misc + M_BE1;
#pragma unroll
        for (int o = 0; o < H; o += 4) {
          const float4 pA = *reinterpret_cast<const float4*>(Pr0 + o);
          const float4 qA = *reinterpret_cast<const float4*>(Qc0 + o);
          const float4 pB = *reinterpret_cast<const float4*>(Pr1 + o);
          const float4 qB = *reinterpret_cast<const float4*>(Qc1 + o);
          const float4 wv = *reinterpret_cast<const float4*>(wr + o);
          const float4 ev = *reinterpret_cast<const float4*>(we + o);
          const float4 bv = *reinterpret_cast<const float4*>(bb + o);
          sth2(me0 + o,     silu_f(pA.x + qA.x + rad0 * wv.x + ea0 * ev.x + bv.x),
                            silu_f(pA.y + qA.y + rad0 * wv.y + ea0 * ev.y + bv.y));
          sth2(me0 + o + 2, silu_f(pA.z + qA.z + rad0 * wv.z + ea0 * ev.z + bv.z),
                            silu_f(pA.w + qA.w + rad0 * wv.w + ea0 * ev.w + bv.w));
          sth2(me1 + o,     silu_f(pB.x + qB.x + rad1 * wv.x + ea1 * ev.x + bv.x),
                            silu_f(pB.y + qB.y + rad1 * wv.y + ea1 * ev.y + bv.y));
          sth2(me1 + o + 2, silu_f(pB.z + qB.z + rad1 * wv.z + ea1 * ev.z + bv.z),
                            silu_f(pB.w + qB.w + rad1 * wv.w + ea1 * ev.w + bv.w));
        }
      }

      // GEMV2 half-width x2, m2 half-0 held as packed fp16 (16 regs/edge)
      uint32_t h0e0[16], h0e1[16];
      float att0 = s.misc[M_BATT], att1 = att0;
      unsigned long long a0[16], a1[16];
      const unsigned long long* be2p =
          reinterpret_cast<const unsigned long long*>(s.misc + M_BE2);
      const ulonglong2* W2 = reinterpret_cast<const ulonglong2*>(s.Wm);
      // half 0 (outputs 0..31)
#pragma unroll
      for (int i = 0; i < 16; i++) { a0[i] = be2p[i]; a1[i] = be2p[i]; }
#pragma unroll 2
      for (int k0 = 0; k0 < H; k0 += 2) {
        const float2 v0 = ldh2(me0 + k0);
        const float2 v1 = ldh2(me1 + k0);
        ghalf2(a0, a1, W2 + (k0 + 0) * 16, splat2(v0.x), splat2(v1.x));
        ghalf2(a0, a1, W2 + (k0 + 1) * 16, splat2(v0.y), splat2(v1.y));
      }
#pragma unroll
      for (int i = 0; i < 16; i++) {
        float p, q;
        unpack2(a0[i], p, q);
        p = silu_f(p); q = silu_f(q);
        att0 += p * s.misc[M_WATT + 2 * i] + q * s.misc[M_WATT + 2 * i + 1];
        h0e0[i] = h2pack(p, q);
        unpack2(a1[i], p, q);
        p = silu_f(p); q = silu_f(q);
        att1 += p * s.misc[M_WATT + 2 * i] + q * s.misc[M_WATT + 2 * i + 1];
        h0e1[i] = h2pack(p, q);
      }
      // half 1 (outputs 32..63)
#pragma unroll
      for (int i = 0; i < 16; i++) { a0[i] = be2p[16 + i]; a1[i] = be2p[16 + i]; }
#pragma unroll 2
      for (int k0 = 0; k0 < H; k0 += 2) {
        const float2 v0 = ldh2(me0 + k0);
        const float2 v1 = ldh2(me1 + k0);
        ghalf2(a0, a1, W2 + (k0 + 0) * 16 + 8, splat2(v0.x), splat2(v1.x));
        ghalf2(a0, a1, W2 + (k0 + 1) * 16 + 8, splat2(v0.y), splat2(v1.y));
      }
#pragma unroll
      for (int i = 0; i < 16; i++) {
        float p, q;
        unpack2(a0[i], p, q);
        p = silu_f(p); q = silu_f(q);
        att0 += p * s.misc[M_WATT + 32 + 2 * i] + q * s.misc[M_WATT + 32 + 2 * i + 1];
        a0[i] = pack2(p, q);
        unpack2(a1[i], p, q);
        p = silu_f(p); q = silu_f(q);
        att1 += p * s.misc[M_WATT + 32 + 2 * i] + q * s.misc[M_WATT + 32 + 2 * i + 1];
        a1[i] = pack2(p, q);
      }
      const float sg0 = __fdividef(1.0f, 1.0f + __expf(-att0));
      const float sg1 = __fdividef(1.0f, 1.0f + __expf(-att1));
      // store GATED m2 (all m1 reads complete)
#pragma unroll
      for (int i = 0; i < 16; i++) {
        float2 f = h2unpack(h0e0[i]);
        sth2(me0 + 2 * i, f.x * sg0, f.y * sg0);
        f = h2unpack(h0e1[i]);
        sth2(me1 + 2 * i, f.x * sg1, f.y * sg1);
        float p, q;
        unpack2(a0[i], p, q);
        sth2(me0 + 32 + 2 * i, p * sg0, q * sg0);
        unpack2(a1[i], p, q);
        sth2(me1 + 32 + 2 * i, p * sg1, q * sg1);
      }
    }
    __syncthreads();
    cp_f4(s.Wm, Wc1 + l * H * H, H * H, tid);
    __syncthreads();

    // ---------- edge pass B: GEMVc -> phi -> trans ----------
    if (tid < ND) {
      const int e0 = tid, e1 = tid + ND;
      const int r0 = e0 / (NP - 1), j0 = e0 % (NP - 1);
      const int c0 = j0 + (j0 >= r0 ? 1 : 0);
      const int r1 = e1 / (NP - 1), j1 = e1 % (NP - 1);
      const int c1 = j1 + (j1 >= r1 ? 1 : 0);
      const __half* me0 = s.m + e0 * MSH;
      const __half* me1 = s.m + e1 * MSH;
      const ulonglong2* Wc = reinterpret_cast<const ulonglong2*>(s.Wm);
      const unsigned long long* bcp =
          reinterpret_cast<const unsigned long long*>(s.misc + M_BC1);
      float phi0 = 0.0f, phi1 = 0.0f;
#pragma unroll 1
      for (int half = 0; half < 2; half++) {
        unsigned long long a0[16], a1[16];
#pragma unroll
        for (int i = 0; i < 16; i++) { a0[i] = bcp[half * 16 + i]; a1[i] = bcp[half * 16 + i]; }
#pragma unroll 2
        for (int k0 = 0; k0 < H; k0 += 2) {
          const float2 v0 = ldh2(me0 + k0);
          const float2 v1 = ldh2(me1 + k0);
          ghalf2(a0, a1, Wc + (k0 + 0) * 16 + half * 8, splat2(v0.x), splat2(v1.x));
          ghalf2(a0, a1, Wc + (k0 + 1) * 16 + half * 8, splat2(v0.y), splat2(v1.y));
        }
#pragma unroll
        for (int i = 0; i < 16; i++) {
          float p, q;
          unpack2(a0[i], p, q);
          phi0 += silu_f(p) * s.misc[M_WC2 + half * 32 + 2 * i]
                + silu_f(q) * s.misc[M_WC2 + half * 32 + 2 * i + 1];
          unpack2(a1[i], p, q);
          phi1 += silu_f(p) * s.misc[M_WC2 + half * 32 + 2 * i]
                + silu_f(q) * s.misc[M_WC2 + half * 32 + 2 * i + 1];
        }
      }
      const float th0 = tanhf(phi0) * 3.0f;   // COORDS_RANGE
      const float th1 = tanhf(phi1) * 3.0f;
#pragma unroll
      for (int d = 0; d < 3; d++) {
        s.trans[e0 * 3 + d] = (s.coord[r0 * 3 + d] - s.coord[c0 * 3 + d]) * th0;
        s.trans[e1 * 3 + d] = (s.coord[r1 * 3 + d] - s.coord[c1 * 3 + d]) * th1;
      }
    }
    __syncthreads();

    // ---------- agg (fp16 m sum) + coord; Wm <- Wn1 rows 0:64 ----------
    cp_f4(s.Wm, Wn1 + l * 128 * H, H * H, tid);
    for (int task = tid; task < NP * H; task += NT) {
      const int r = task >> 6, o = task & 63;
      const __half* mp = s.m + (r * (NP - 1)) * MSH + o;
      float a = 0.0f;
#pragma unroll
      for (int j = 0; j < NP - 1; j++) a += __half2float(mp[j * MSH]);
      s.agg[r * HSF + o] = a;
    }
    for (int task = tid; task < NP * DD; task += NT) {
      const int r = task / DD, d = task % DD;
      const float* tp = s.trans + (r * (NP - 1)) * DD + d;
      float a = 0.0f;
#pragma unroll
      for (int j = 0; j < NP - 1; j++) a += tp[j * DD];
      s.coord[task] += a;
    }
    __syncthreads();

    // ---------- node GEMV1 part 1 (h input) ----------
    unsigned long long a1v[3];
    {
      const unsigned long long* Wu = reinterpret_cast<const unsigned long long*>(s.Wm);
      const unsigned long long bn1p =
          reinterpret_cast<const unsigned long long*>(s.misc + M_BN1)[lane];
      int rnd = 0;
#pragma unroll 1
      for (int n = w; n < NP; n += NT / 32, rnd++) {
        const float* hn = s.h + n * HSF;
        unsigned long long acc = bn1p;
#pragma unroll 4
        for (int k = 0; k < H; k++) acc = ffma2(splat2(hn[k]), Wu[k * 32 + lane], acc);
        a1v[rnd] = acc;
      }
    }
    __syncthreads();
    cp_f4(s.Wm, Wn1 + l * 128 * H + H * H, H * H, tid);   // rows 64:128
    __syncthreads();

    // ---------- node GEMV1 part 2 (agg input) -> hidden (fp32 in m buffer) ----------
    {
      float* hid = reinterpret_cast<float*>(s.m);
      const unsigned long long* Wu = reinterpret_cast<const unsigned long long*>(s.Wm);
      int rnd = 0;
#pragma unroll 1
      for (int n = w; n < NP; n += NT / 32, rnd++) {
        const float* an = s.agg + n * HSF;
        unsigned long long acc = a1v[rnd];
#pragma unroll 4
        for (int k = 0; k < H; k++) acc = ffma2(splat2(an[k]), Wu[k * 32 + lane], acc);
        float lo, hi; unpack2(acc, lo, hi);
        reinterpret_cast<unsigned long long*>(hid)[n * 32 + lane] =
            pack2(silu_f(lo), silu_f(hi));
      }
    }
    __syncthreads();
    cp_f4(s.Wm, Wn2 + l * H * H, H * H, tid);
    __syncthreads();

    // ---------- node GEMV2: h += hidden @ Wn2 + bn2 ----------
    {
      const float* hid = reinterpret_cast<const float*>(s.m);
      const unsigned long long* Wu = reinterpret_cast<const unsigned long long*>(s.Wm);
      const unsigned long long bn2p =
          reinterpret_cast<const unsigned long long*>(s.misc + M_BN2)[lane];
#pragma unroll 1
      for (int n = w; n < NP; n += NT / 32) {
        const float* hn = hid + n * H;
        unsigned long long acc = bn2p;
#pragma unroll 4
        for (int k = 0; k < H; k++) acc = ffma2(splat2(hn[k]), Wu[k * 32 + lane], acc);
        float lo, hi; unpack2(acc, lo, hi);
        s.h[n * HSF + 2 * lane]     += lo;
        s.h[n * HSF + 2 * lane + 1] += hi;
      }
    }
    __syncthreads();
  }

  // ---------- output: vel = (coord - x) - mean_over_particles ----------
  if (tid < DD) {
    float mm = 0.0f;
    for (int i = 0; i < NP; i++)
      mm += s.coord[i * DD + tid] - x[b * (NP * DD) + i * DD + tid];
    s.ea[tid] = mm * (1.0f / NP);
  }
  __syncthreads();
  for (int task = tid; task < NP * DD; task += NT) {
    out[b * (NP * DD) + task] =
        (s.coord[task] - x[b * (NP * DD) + task]) - s.ea[task % DD];
  }
}

}  // namespace

extern "C" void kernel_launch(void* const* d_in, const int* in_sizes, int n_in,
                              void* d_out, int out_size) {
  (void)in_sizes; (void)n_in; (void)out_size;
  const float* t      = (const float*)d_in[0];
  const float* x      = (const float*)d_in[1];
  const float* h_init = (const float*)d_in[2];
  // d_in[3]/d_in[4] rows/cols: fixed fully-connected pattern, derived analytically
  const float* Wemb = (const float*)d_in[5];
  const float* bemb = (const float*)d_in[6];
  const float* We1  = (const float*)d_in[7];
  const float* be1  = (const float*)d_in[8];
  const float* We2  = (const float*)d_in[9];
  const float* be2  = (const float*)d_in[10];
  const float* Watt = (const float*)d_in[11];
  const float* batt = (const float*)d_in[12];
  const float* Wn1  = (const float*)d_in[13];
  const float* bn1  = (const float*)d_in[14];
  const float* Wn2  = (const float*)d_in[15];
  const float* bn2  = (const float*)d_in[16];
  const float* Wc1  = (const float*)d_in[17];
  const float* bc1  = (const float*)d_in[18];
  const float* Wc2  = (const float*)d_in[19];

  cudaFuncSetAttribute(egnn_kernel, cudaFuncAttributeMaxDynamicSharedMemorySize,
                       (int)sizeof(Smem));
  egnn_kernel<<<B, NT, sizeof(Smem)>>>(t, x, h_init, Wemb, bemb, We1, be1, We2, be2,
                                       Watt, batt, Wn1, bn1, Wn2, bn2, Wc1, bc1, Wc2,
                                       (float*)d_out);
}

// round 15
// speedup vs baseline: 10.1794x; 1.0257x over previous
#include <cuda_runtime.h>
#include <cuda_fp16.h>
#include <cstdint>

namespace {

constexpr int B   = 1024;
constexpr int NP  = 22;
constexpr int DD  = 3;
constexpr int H   = 64;
constexpr int L   = 5;
constexpr int EPB = NP * (NP - 1);   // 462 edges
constexpr int ND  = 231;             // dual-edge threads
constexpr int HSF = 68;              // fp32 h/P/Q/agg stride (floats)
constexpr int MSH = 68;              // fp16 m stride (halves): 136B rows -> 8B-aligned, conflict-free
constexpr int NT  = 256;             // 8 warps; 2 CTAs/SM via 128-reg cap

// misc (fp32) offsets
constexpr int M_WE1R = 0;    // We1 rows 128,129 (128 floats)
constexpr int M_BE1  = 128;
constexpr int M_BE2  = 192;
constexpr int M_BC1  = 256;
constexpr int M_WATT = 320;
constexpr int M_WC2  = 384;
constexpr int M_BN1  = 448;
constexpr int M_BN2  = 512;
constexpr int M_BATT = 576;
constexpr int M_SZ   = 640;

struct __align__(16) Smem {
  float  Wm[4096];          // 16,384 B  overlay: We1lo/We1hi/We2/Wc1/Wn1lo/Wn1hi/Wn2
  float  misc[M_SZ];        //  2,560 B
  float  h[NP * HSF];       //  5,984 B
  float  P[NP * HSF];       //  5,984 B  fp32 (precision-critical)
  float  Q[NP * HSF];       //  5,984 B  fp32
  float  agg[NP * HSF];     //  5,984 B
  float  ea[EPB];           //  1,848 B
  float  trans[EPB * DD];   //  5,544 B
  float  coord[NP * DD];    //    264 B
  __half m[EPB * MSH];      // 62,832 B  m1 then GATED m2; reused as fp32 node-hidden
};                          // 113,368 B -> same 112KB-bucket, 2 CTAs/SM

// ---------------- packed f32x2 helpers ----------------
__device__ __forceinline__ unsigned long long splat2(float v) {
  unsigned long long r; unsigned int u = __float_as_uint(v);
  asm("mov.b64 %0, {%1, %1};" : "=l"(r) : "r"(u)); return r;
}
__device__ __forceinline__ unsigned long long pack2(float a, float b) {
  unsigned long long r;
  asm("mov.b64 %0, {%1, %2};" : "=l"(r) : "r"(__float_as_uint(a)), "r"(__float_as_uint(b)));
  return r;
}
__device__ __forceinline__ unsigned long long ffma2(unsigned long long a,
                                                    unsigned long long b,
                                                    unsigned long long c) {
  unsigned long long d;
  asm("fma.rn.f32x2 %0, %1, %2, %3;" : "=l"(d) : "l"(a), "l"(b), "l"(c));
  return d;
}
__device__ __forceinline__ void unpack2(unsigned long long v, float& lo, float& hi) {
  unsigned int a, b;
  asm("mov.b64 {%0, %1}, %2;" : "=r"(a), "=r"(b) : "l"(v));
  lo = __uint_as_float(a); hi = __uint_as_float(b);
}
__device__ __forceinline__ float silu_f(float x) {
  return __fdividef(x, 1.0f + __expf(-x));
}
__device__ __forceinline__ uint32_t h2pack(float a, float b) {
  __half2 h = __floats2half2_rn(a, b);
  return *reinterpret_cast<uint32_t*>(&h);
}
__device__ __forceinline__ float2 h2unpack(uint32_t u) {
  __half2 h = *reinterpret_cast<__half2*>(&u);
  return __half22float2(h);
}

// half-width (32 outputs) k-step, TWO edges: each LDS.128 feeds 4 FFMA2
__device__ __forceinline__ void ghalf2(unsigned long long a0[16],
                                       unsigned long long a1[16],
                                       const ulonglong2* __restrict__ wrow,
                                       unsigned long long in0,
                                       unsigned long long in1) {
#pragma unroll
  for (int i = 0; i < 8; i++) {
    ulonglong2 u = wrow[i];                 // broadcast LDS.128
    a0[2 * i]     = ffma2(in0, u.x, a0[2 * i]);
    a1[2 * i]     = ffma2(in1, u.x, a1[2 * i]);
    a0[2 * i + 1] = ffma2(in0, u.y, a0[2 * i + 1]);
    a1[2 * i + 1] = ffma2(in1, u.y, a1[2 * i + 1]);
  }
}

// one GEMV half-pass (32 outputs) over 64 fp16 inputs for two edges, LDS.64 inputs
__device__ __forceinline__ void gemv_half(unsigned long long a0[16],
                                          unsigned long long a1[16],
                                          const __half* __restrict__ me0,
                                          const __half* __restrict__ me1,
                                          const ulonglong2* __restrict__ Wh) {
#pragma unroll 2
  for (int k0 = 0; k0 < H; k0 += 4) {
    const uint2 u0 = *reinterpret_cast<const uint2*>(me0 + k0);   // LDS.64: 4 halves
    const uint2 u1 = *reinterpret_cast<const uint2*>(me1 + k0);
    const float2 v0a = h2unpack(u0.x), v0b = h2unpack(u0.y);
    const float2 v1a = h2unpack(u1.x), v1b = h2unpack(u1.y);
    ghalf2(a0, a1, Wh + (k0 + 0) * 16, splat2(v0a.x), splat2(v1a.x));
    ghalf2(a0, a1, Wh + (k0 + 1) * 16, splat2(v0a.y), splat2(v1a.y));
    ghalf2(a0, a1, Wh + (k0 + 2) * 16, splat2(v0b.x), splat2(v1b.x));
    ghalf2(a0, a1, Wh + (k0 + 3) * 16, splat2(v0b.y), splat2(v1b.y));
  }
}

__device__ __forceinline__ void cp_f4(float* dst, const float* __restrict__ src,
                                      int nfloats, int tid) {
  float4* d = reinterpret_cast<float4*>(dst);
  const float4* s = reinterpret_cast<const float4*>(src);
  for (int i = tid; i < (nfloats >> 2); i += NT) d[i] = s[i];
}

__global__ void __launch_bounds__(NT, 2)        // 128-reg cap -> 2 CTAs/SM
egnn_kernel(const float* __restrict__ t, const float* __restrict__ x,
            const float* __restrict__ h_init,
            const float* __restrict__ Wemb, const float* __restrict__ bemb,
            const float* __restrict__ We1,  const float* __restrict__ be1,
            const float* __restrict__ We2,  const float* __restrict__ be2,
            const float* __restrict__ Watt, const float* __restrict__ batt,
            const float* __restrict__ Wn1,  const float* __restrict__ bn1,
            const float* __restrict__ Wn2,  const float* __restrict__ bn2,
            const float* __restrict__ Wc1,  const float* __restrict__ bc1,
            const float* __restrict__ Wc2,
            float* __restrict__ out)
{
  extern __shared__ char smem_raw[];
  Smem& s = *reinterpret_cast<Smem*>(smem_raw);
  const int b    = blockIdx.x;
  const int tid  = threadIdx.x;
  const int w    = tid >> 5;
  const int lane = tid & 31;

  // ---------- node embedding ----------
  const float tb = t[b];
  for (int task = tid; task < NP * H; task += NT) {
    const int i = task / H, o = task % H;
    float acc = bemb[o] + tb * Wemb[NP * H + o];
#pragma unroll
    for (int j = 0; j < NP; j++) acc += h_init[i * NP + j] * Wemb[j * H + o];
    s.h[i * HSF + o] = acc;
  }
  for (int task = tid; task < NP * DD; task += NT)
    s.coord[task] = x[b * (NP * DD) + task];
  __syncthreads();

  for (int e = tid; e < EPB; e += NT) {
    const int r = e / (NP - 1), jj = e % (NP - 1);
    const int c = jj + (jj >= r ? 1 : 0);
    const float dx = s.coord[r * 3 + 0] - s.coord[c * 3 + 0];
    const float dy = s.coord[r * 3 + 1] - s.coord[c * 3 + 1];
    const float dz = s.coord[r * 3 + 2] - s.coord[c * 3 + 2];
    s.ea[e] = dx * dx + dy * dy + dz * dz;
  }

  for (int l = 0; l < L; l++) {
    // ---------- misc + Wm <- We1 rows 0:64 ----------
    __syncthreads();
    cp_f4(s.misc + M_WE1R, We1 + l * 130 * H + 128 * H, 2 * H, tid);
    cp_f4(s.misc + M_BE1,  be1 + l * H, H, tid);
    cp_f4(s.misc + M_BE2,  be2 + l * H, H, tid);
    cp_f4(s.misc + M_BC1,  bc1 + l * H, H, tid);
    cp_f4(s.misc + M_WATT, Watt + l * H, H, tid);
    cp_f4(s.misc + M_WC2,  Wc2 + l * H, H, tid);
    cp_f4(s.misc + M_BN1,  bn1 + l * H, H, tid);
    cp_f4(s.misc + M_BN2,  bn2 + l * H, H, tid);
    if (tid == 0) s.misc[M_BATT] = batt[l];
    cp_f4(s.Wm, We1 + l * 130 * H, H * H, tid);
    __syncthreads();

    // ---------- P pass: P_n = h_n @ We1[0:64] (fp32) ----------
    {
      const unsigned long long* Wu = reinterpret_cast<const unsigned long long*>(s.Wm);
#pragma unroll 1
      for (int n = w; n < NP; n += NT / 32) {
        const float* hn = s.h + n * HSF;
        unsigned long long acc = 0ull;
#pragma unroll 4
        for (int k = 0; k < H; k++) acc = ffma2(splat2(hn[k]), Wu[k * 32 + lane], acc);
        reinterpret_cast<unsigned long long*>(s.P + n * HSF)[lane] = acc;
      }
    }
    __syncthreads();
    cp_f4(s.Wm, We1 + l * 130 * H + H * H, H * H, tid);   // rows 64:128
    __syncthreads();

    // ---------- Q pass: Q_n = h_n @ We1[64:128] (fp32) ----------
    {
      const unsigned long long* Wu = reinterpret_cast<const unsigned long long*>(s.Wm);
#pragma unroll 1
      for (int n = w; n < NP; n += NT / 32) {
        const float* hn = s.h + n * HSF;
        unsigned long long acc = 0ull;
#pragma unroll 4
        for (int k = 0; k < H; k++) acc = ffma2(splat2(hn[k]), Wu[k * 32 + lane], acc);
        reinterpret_cast<unsigned long long*>(s.Q + n * HSF)[lane] = acc;
      }
    }
    __syncthreads();
    cp_f4(s.Wm, We2 + l * H * H, H * H, tid);
    __syncthreads();

    // ---------- edge pass A: m1 assembly + GEMV2 + gate (tid < 231) ----------
    if (tid < ND) {
      const int e0 = tid, e1 = tid + ND;
      const int r0 = e0 / (NP - 1), j0 = e0 % (NP - 1);
      const int c0 = j0 + (j0 >= r0 ? 1 : 0);
      const int r1 = e1 / (NP - 1), j1 = e1 % (NP - 1);
      const int c1 = j1 + (j1 >= r1 ? 1 : 0);
      float rad0, rad1;
      {
        const float dx0 = s.coord[r0 * 3 + 0] - s.coord[c0 * 3 + 0];
        const float dy0 = s.coord[r0 * 3 + 1] - s.coord[c0 * 3 + 1];
        const float dz0 = s.coord[r0 * 3 + 2] - s.coord[c0 * 3 + 2];
        const float dx1 = s.coord[r1 * 3 + 0] - s.coord[c1 * 3 + 0];
        const float dy1 = s.coord[r1 * 3 + 1] - s.coord[c1 * 3 + 1];
        const float dz1 = s.coord[r1 * 3 + 2] - s.coord[c1 * 3 + 2];
        rad0 = dx0 * dx0 + dy0 * dy0 + dz0 * dz0;
        rad1 = dx1 * dx1 + dy1 * dy1 + dz1 * dz1;
      }
      const float ea0 = s.ea[e0], ea1 = s.ea[e1];
      __half* me0 = s.m + e0 * MSH;
      __half* me1 = s.m + e1 * MSH;

      // m1 = silu(P_r + Q_c + rad*We1r128 + ea*We1r129 + be1) (fp32 in, STS.64 fp16 out)
      {
        const float* Pr0 = s.P + r0 * HSF;
        const float* Qc0 = s.Q + c0 * HSF;
        const float* Pr1 = s.P + r1 * HSF;
        const float* Qc1 = s.Q + c1 * HSF;
        const float* wr = s.misc + M_WE1R;
        const float* we = s.misc + M_WE1R + H;
        const float* bb = s.misc + M_BE1;
#pragma unroll
        for (int o = 0; o < H; o += 4) {
          const float4 pA = *reinterpret_cast<const float4*>(Pr0 + o);
          const float4 qA = *reinterpret_cast<const float4*>(Qc0 + o);
          const float4 pB = *reinterpret_cast<const float4*>(Pr1 + o);
          const float4 qB = *reinterpret_cast<const float4*>(Qc1 + o);
          const float4 wv = *reinterpret_cast<const float4*>(wr + o);
          const float4 ev = *reinterpret_cast<const float4*>(we + o);
          const float4 bv = *reinterpret_cast<const float4*>(bb + o);
          uint2 st;
          st.x = h2pack(silu_f(pA.x + qA.x + rad0 * wv.x + ea0 * ev.x + bv.x),
                        silu_f(pA.y + qA.y + rad0 * wv.y + ea0 * ev.y + bv.y));
          st.y = h2pack(silu_f(pA.z + qA.z + rad0 * wv.z + ea0 * ev.z + bv.z),
                        silu_f(pA.w + qA.w + rad0 * wv.w + ea0 * ev.w + bv.w));
          *reinterpret_cast<uint2*>(me0 + o) = st;          // STS.64
          st.x = h2pack(silu_f(pB.x + qB.x + rad1 * wv.x + ea1 * ev.x + bv.x),
                        silu_f(pB.y + qB.y + rad1 * wv.y + ea1 * ev.y + bv.y));
          st.y = h2pack(silu_f(pB.z + qB.z + rad1 * wv.z + ea1 * ev.z + bv.z),
                        silu_f(pB.w + qB.w + rad1 * wv.w + ea1 * ev.w + bv.w));
          *reinterpret_cast<uint2*>(me1 + o) = st;
        }
      }

      // GEMV2 half-width x2, m2 half-0 held as packed fp16 (16 regs/edge)
      uint32_t h0e0[16], h0e1[16];
      float att0 = s.misc[M_BATT], att1 = att0;
      unsigned long long a0[16], a1[16];
      const unsigned long long* be2p =
          reinterpret_cast<const unsigned long long*>(s.misc + M_BE2);
      const ulonglong2* W2 = reinterpret_cast<const ulonglong2*>(s.Wm);
      // half 0 (outputs 0..31)
#pragma unroll
      for (int i = 0; i < 16; i++) { a0[i] = be2p[i]; a1[i] = be2p[i]; }
      gemv_half(a0, a1, me0, me1, W2);
#pragma unroll
      for (int i = 0; i < 16; i++) {
        float p, q;
        unpack2(a0[i], p, q);
        p = silu_f(p); q = silu_f(q);
        att0 += p * s.misc[M_WATT + 2 * i] + q * s.misc[M_WATT + 2 * i + 1];
        h0e0[i] = h2pack(p, q);
        unpack2(a1[i], p, q);
        p = silu_f(p); q = silu_f(q);
        att1 += p * s.misc[M_WATT + 2 * i] + q * s.misc[M_WATT + 2 * i + 1];
        h0e1[i] = h2pack(p, q);
      }
      // half 1 (outputs 32..63)
#pragma unroll
      for (int i = 0; i < 16; i++) { a0[i] = be2p[16 + i]; a1[i] = be2p[16 + i]; }
      gemv_half(a0, a1, me0, me1, W2 + 8);
#pragma unroll
      for (int i = 0; i < 16; i++) {
        float p, q;
        unpack2(a0[i], p, q);
        p = silu_f(p); q = silu_f(q);
        att0 += p * s.misc[M_WATT + 32 + 2 * i] + q * s.misc[M_WATT + 32 + 2 * i + 1];
        a0[i] = pack2(p, q);
        unpack2(a1[i], p, q);
        p = silu_f(p); q = silu_f(q);
        att1 += p * s.misc[M_WATT + 32 + 2 * i] + q * s.misc[M_WATT + 32 + 2 * i + 1];
        a1[i] = pack2(p, q);
      }
      const float sg0 = __fdividef(1.0f, 1.0f + __expf(-att0));
      const float sg1 = __fdividef(1.0f, 1.0f + __expf(-att1));
      // store GATED m2 via STS.64 (all m1 reads complete)
#pragma unroll
      for (int i = 0; i < 8; i++) {
        float2 fa = h2unpack(h0e0[2 * i]);
        float2 fb = h2unpack(h0e0[2 * i + 1]);
        uint2 st;
        st.x = h2pack(fa.x * sg0, fa.y * sg0);
        st.y = h2pack(fb.x * sg0, fb.y * sg0);
        *reinterpret_cast<uint2*>(me0 + 4 * i) = st;
        fa = h2unpack(h0e1[2 * i]);
        fb = h2unpack(h0e1[2 * i + 1]);
        st.x = h2pack(fa.x * sg1, fa.y * sg1);
        st.y = h2pack(fb.x * sg1, fb.y * sg1);
        *reinterpret_cast<uint2*>(me1 + 4 * i) = st;
      }
#pragma unroll
      for (int i = 0; i < 8; i++) {
        float pa, qa, pb, qb;
        unpack2(a0[2 * i], pa, qa);
        unpack2(a0[2 * i + 1], pb, qb);
        uint2 st;
        st.x = h2pack(pa * sg0, qa * sg0);
        st.y = h2pack(pb * sg0, qb * sg0);
        *reinterpret_cast<uint2*>(me0 + 32 + 4 * i) = st;
        unpack2(a1[2 * i], pa, qa);
        unpack2(a1[2 * i + 1], pb, qb);
        st.x = h2pack(pa * sg1, qa * sg1);
        st.y = h2pack(pb * sg1, qb * sg1);
        *reinterpret_cast<uint2*>(me1 + 32 + 4 * i) = st;
      }
    }
    __syncthreads();
    cp_f4(s.Wm, Wc1 + l * H * H, H * H, tid);
    __syncthreads();

    // ---------- edge pass B: GEMVc -> phi -> trans ----------
    if (tid < ND) {
      const int e0 = tid, e1 = tid + ND;
      const int r0 = e0 / (NP - 1), j0 = e0 % (NP - 1);
      const int c0 = j0 + (j0 >= r0 ? 1 : 0);
      const int r1 = e1 / (NP - 1), j1 = e1 % (NP - 1);
      const int c1 = j1 + (j1 >= r1 ? 1 : 0);
      const __half* me0 = s.m + e0 * MSH;
      const __half* me1 = s.m + e1 * MSH;
      const ulonglong2* Wc = reinterpret_cast<const ulonglong2*>(s.Wm);
      const unsigned long long* bcp =
          reinterpret_cast<const unsigned long long*>(s.misc + M_BC1);
      float phi0 = 0.0f, phi1 = 0.0f;
#pragma unroll 1
      for (int half = 0; half < 2; half++) {
        unsigned long long a0[16], a1[16];
#pragma unroll
        for (int i = 0; i < 16; i++) { a0[i] = bcp[half * 16 + i]; a1[i] = bcp[half * 16 + i]; }
        gemv_half(a0, a1, me0, me1, Wc + half * 8);
#pragma unroll
        for (int i = 0; i < 16; i++) {
          float p, q;
          unpack2(a0[i], p, q);
          phi0 += silu_f(p) * s.misc[M_WC2 + half * 32 + 2 * i]
                + silu_f(q) * s.misc[M_WC2 + half * 32 + 2 * i + 1];
          unpack2(a1[i], p, q);
          phi1 += silu_f(p) * s.misc[M_WC2 + half * 32 + 2 * i]
                + silu_f(q) * s.misc[M_WC2 + half * 32 + 2 * i + 1];
        }
      }
      const float th0 = tanhf(phi0) * 3.0f;   // COORDS_RANGE
      const float th1 = tanhf(phi1) * 3.0f;
#pragma unroll
      for (int d = 0; d < 3; d++) {
        s.trans[e0 * 3 + d] = (s.coord[r0 * 3 + d] - s.coord[c0 * 3 + d]) * th0;
        s.trans[e1 * 3 + d] = (s.coord[r1 * 3 + d] - s.coord[c1 * 3 + d]) * th1;
      }
    }
    __syncthreads();

    // ---------- agg (fp16 m sum) + coord; Wm <- Wn1 rows 0:64 ----------
    cp_f4(s.Wm, Wn1 + l * 128 * H, H * H, tid);
    for (int task = tid; task < NP * H; task += NT) {
      const int r = task >> 6, o = task & 63;
      const __half* mp = s.m + (r * (NP - 1)) * MSH + o;
      float a = 0.0f;
#pragma unroll
      for (int j = 0; j < NP - 1; j++) a += __half2float(mp[j * MSH]);
      s.agg[r * HSF + o] = a;
    }
    for (int task = tid; task < NP * DD; task += NT) {
      const int r = task / DD, d = task % DD;
      const float* tp = s.trans + (r * (NP - 1)) * DD + d;
      float a = 0.0f;
#pragma unroll
      for (int j = 0; j < NP - 1; j++) a += tp[j * DD];
      s.coord[task] += a;
    }
    __syncthreads();

    // ---------- node GEMV1 part 1 (h input) ----------
    unsigned long long a1v[3];
    {
      const unsigned long long* Wu = reinterpret_cast<const unsigned long long*>(s.Wm);
      const unsigned long long bn1p =
          reinterpret_cast<const unsigned long long*>(s.misc + M_BN1)[lane];
      int rnd = 0;
#pragma unroll 1
      for (int n = w; n < NP; n += NT / 32, rnd++) {
        const float* hn = s.h + n * HSF;
        unsigned long long acc = bn1p;
#pragma unroll 4
        for (int k = 0; k < H; k++) acc = ffma2(splat2(hn[k]), Wu[k * 32 + lane], acc);
        a1v[rnd] = acc;
      }
    }
    __syncthreads();
    cp_f4(s.Wm, Wn1 + l * 128 * H + H * H, H * H, tid);   // rows 64:128
    __syncthreads();

    // ---------- node GEMV1 part 2 (agg input) -> hidden (fp32 in m buffer) ----------
    {
      float* hid = reinterpret_cast<float*>(s.m);
      const unsigned long long* Wu = reinterpret_cast<const unsigned long long*>(s.Wm);
      int rnd = 0;
#pragma unroll 1
      for (int n = w; n < NP; n += NT / 32, rnd++) {
        const float* an = s.agg + n * HSF;
        unsigned long long acc = a1v[rnd];
#pragma unroll 4
        for (int k = 0; k < H; k++) acc = ffma2(splat2(an[k]), Wu[k * 32 + lane], acc);
        float lo, hi; unpack2(acc, lo, hi);
        reinterpret_cast<unsigned long long*>(hid)[n * 32 + lane] =
            pack2(silu_f(lo), silu_f(hi));
      }
    }
    __syncthreads();
    cp_f4(s.Wm, Wn2 + l * H * H, H * H, tid);
    __syncthreads();

    // ---------- node GEMV2: h += hidden @ Wn2 + bn2 ----------
    {
      const float* hid = reinterpret_cast<const float*>(s.m);
      const unsigned long long* Wu = reinterpret_cast<const unsigned long long*>(s.Wm);
      const unsigned long long bn2p =
          reinterpret_cast<const unsigned long long*>(s.misc + M_BN2)[lane];
#pragma unroll 1
      for (int n = w; n < NP; n += NT / 32) {
        const float* hn = hid + n * H;
        unsigned long long acc = bn2p;
#pragma unroll 4
        for (int k = 0; k < H; k++) acc = ffma2(splat2(hn[k]), Wu[k * 32 + lane], acc);
        float lo, hi; unpack2(acc, lo, hi);
        s.h[n * HSF + 2 * lane]     += lo;
        s.h[n * HSF + 2 * lane + 1] += hi;
      }
    }
    __syncthreads();
  }

  // ---------- output: vel = (coord - x) - mean_over_particles ----------
  if (tid < DD) {
    float mm = 0.0f;
    for (int i = 0; i < NP; i++)
      mm += s.coord[i * DD + tid] - x[b * (NP * DD) + i * DD + tid];
    s.ea[tid] = mm * (1.0f / NP);
  }
  __syncthreads();
  for (int task = tid; task < NP * DD; task += NT) {
    out[b * (NP * DD) + task] =
        (s.coord[task] - x[b * (NP * DD) + task]) - s.ea[task % DD];
  }
}

}  // namespace

extern "C" void kernel_launch(void* const* d_in, const int* in_sizes, int n_in,
                              void* d_out, int out_size) {
  (void)in_sizes; (void)n_in; (void)out_size;
  const float* t      = (const float*)d_in[0];
  const float* x      = (const float*)d_in[1];
  const float* h_init = (const float*)d_in[2];
  // d_in[3]/d_in[4] rows/cols: fixed fully-connected pattern, derived analytically
  const float* Wemb = (const float*)d_in[5];
  const float* bemb = (const float*)d_in[6];
  const float* We1  = (const float*)d_in[7];
  const float* be1  = (const float*)d_in[8];
  const float* We2  = (const float*)d_in[9];
  const float* be2  = (const float*)d_in[10];
  const float* Watt = (const float*)d_in[11];
  const float* batt = (const float*)d_in[12];
  const float* Wn1  = (const float*)d_in[13];
  const float* bn1  = (const float*)d_in[14];
  const float* Wn2  = (const float*)d_in[15];
  const float* bn2  = (const float*)d_in[16];
  const float* Wc1  = (const float*)d_in[17];
  const float* bc1  = (const float*)d_in[18];
  const float* Wc2  = (const float*)d_in[19];

  cudaFuncSetAttribute(egnn_kernel, cudaFuncAttributeMaxDynamicSharedMemorySize,
                       (int)sizeof(Smem));
  egnn_kernel<<<B, NT, sizeof(Smem)>>>(t, x, h_init, Wemb, bemb, We1, be1, We2, be2,
                                       Watt, batt, Wn1, bn1, Wn2, bn2, Wc1, bc1, Wc2,
                                       (float*)d_out);
}